// round 3
// baseline (speedup 1.0000x reference)
#include <cuda_runtime.h>
#include <math.h>

#define B_SZ    2
#define S_LEN   2048
#define D_MODEL 2048
#define N_HEADS 16
#define HD      128
#define M_ROWS  (B_SZ * S_LEN)   /* 4096 */

/* ------------------------------------------------------------------ */
/* scratch in device globals (no allocation allowed)                   */
/* ------------------------------------------------------------------ */
__device__ float g_q[B_SZ * S_LEN * D_MODEL];
__device__ float g_k[B_SZ * S_LEN * D_MODEL];
__device__ float g_v[B_SZ * S_LEN * D_MODEL];
__device__ float g_attn[B_SZ * S_LEN * D_MODEL];
__device__ float g_cos_tab[S_LEN * (HD / 2)];
__device__ float g_sin_tab[S_LEN * (HD / 2)];

/* ------------------------------------------------------------------ */
/* RoPE cos/sin table, computed in fp64 for accuracy                   */
/* ------------------------------------------------------------------ */
__global__ void rope_table_kernel() {
    int idx = blockIdx.x * blockDim.x + threadIdx.x;
    if (idx >= S_LEN * (HD / 2)) return;
    int s = idx >> 6;          /* position   */
    int i = idx & 63;          /* pair index */
    double inv = pow(10000.0, -(double)(2 * i) / (double)HD);
    double ang = (double)s * inv;
    g_cos_tab[idx] = (float)cos(ang);
    g_sin_tab[idx] = (float)sin(ang);
}

/* ------------------------------------------------------------------ */
/* NT GEMM:  C[m,n] = sum_k A[m,k] * W[n,k]                            */
/* 64x64 tile, KT=16, 256 threads, 4x4 per thread, reg-prefetch.       */
/* rope!=0: apply RoPE to output pairs (q/k projections).              */
/* ------------------------------------------------------------------ */
__global__ void __launch_bounds__(256, 3)
gemm_nt_kernel(const float* __restrict__ A, const float* __restrict__ W,
               float* __restrict__ C, int M, int N, int K, int rope)
{
    __shared__ float As[16 * 68];
    __shared__ float Bs[16 * 68];

    const int t  = threadIdx.x;
    const int tx = t & 15, ty = t >> 4;
    const int m0 = blockIdx.y * 64, n0 = blockIdx.x * 64;

    /* loaders: thread -> (row lr, k-quad lk) */
    const int lr = t >> 2;
    const int lk = (t & 3) * 4;
    const float* aptr = A + (size_t)(m0 + lr) * K + lk;
    const float* bptr = W + (size_t)(n0 + lr) * K + lk;

    float4 apre = *(const float4*)aptr;
    float4 bpre = *(const float4*)bptr;

    float acc[4][4];
#pragma unroll
    for (int i = 0; i < 4; i++)
#pragma unroll
        for (int j = 0; j < 4; j++) acc[i][j] = 0.0f;

    for (int k0 = 0; k0 < K; k0 += 16) {
        /* store prefetched tile transposed: As[k][m] */
        As[(lk + 0) * 68 + lr] = apre.x;
        As[(lk + 1) * 68 + lr] = apre.y;
        As[(lk + 2) * 68 + lr] = apre.z;
        As[(lk + 3) * 68 + lr] = apre.w;
        Bs[(lk + 0) * 68 + lr] = bpre.x;
        Bs[(lk + 1) * 68 + lr] = bpre.y;
        Bs[(lk + 2) * 68 + lr] = bpre.z;
        Bs[(lk + 3) * 68 + lr] = bpre.w;
        __syncthreads();

        if (k0 + 16 < K) {
            apre = *(const float4*)(aptr + k0 + 16);
            bpre = *(const float4*)(bptr + k0 + 16);
        }

#pragma unroll
        for (int kk = 0; kk < 16; kk++) {
            float4 av = *(const float4*)(As + kk * 68 + ty * 4);
            float4 bv = *(const float4*)(Bs + kk * 68 + tx * 4);
            float a[4] = {av.x, av.y, av.z, av.w};
            float b[4] = {bv.x, bv.y, bv.z, bv.w};
#pragma unroll
            for (int i = 0; i < 4; i++)
#pragma unroll
                for (int j = 0; j < 4; j++) acc[i][j] += a[i] * b[j];
        }
        __syncthreads();
    }

    if (rope) {
        const int nbase = n0 + tx * 4;
        const int de    = nbase & (HD - 1);    /* even, multiple of 4 */
#pragma unroll
        for (int i = 0; i < 4; i++) {
            int srow = (m0 + ty * 4 + i) & (S_LEN - 1);
            const float* cb = g_cos_tab + srow * (HD / 2);
            const float* sb = g_sin_tab + srow * (HD / 2);
#pragma unroll
            for (int jp = 0; jp < 2; jp++) {
                int ti = (de >> 1) + jp;
                float c  = cb[ti];
                float sn = sb[ti];
                float xr = acc[i][2 * jp];
                float xi = acc[i][2 * jp + 1];
                acc[i][2 * jp]     = xr * c - xi * sn;
                acc[i][2 * jp + 1] = xr * sn + xi * c;
            }
        }
    }

#pragma unroll
    for (int i = 0; i < 4; i++) {
        float4 r;
        r.x = acc[i][0]; r.y = acc[i][1]; r.z = acc[i][2]; r.w = acc[i][3];
        *(float4*)(C + (size_t)(m0 + ty * 4 + i) * N + n0 + tx * 4) = r;
    }
}

/* ------------------------------------------------------------------ */
/* Flash attention (causal), fp32.                                     */
/* Block: 64 query rows of one (b,h). 256 threads.                     */
/* smem: Qs[64][128] | KV (K^T [128][68] then V [64][132]) | Ps[64][68]*/
/*       | m/l/fac[64]  -> 85760 bytes, 2 CTA/SM.                      */
/* ------------------------------------------------------------------ */
#define FLASH_SMEM_BYTES ((8192 + 8704 + 4352 + 192) * 4)

__global__ void __launch_bounds__(256, 2)
flash_attn_kernel(const float* __restrict__ Qg, const float* __restrict__ Kg,
                  const float* __restrict__ Vg, float* __restrict__ Og)
{
    extern __shared__ float sm[];
    float* Qs  = sm;                 /* 64*128      */
    float* KV  = sm + 8192;          /* max 128*68  */
    float* Ps  = KV + 8704;          /* 64*68       */
    float* m_s = Ps + 4352;          /* 64          */
    float* l_s = m_s + 64;           /* 64          */
    float* f_s = l_s + 64;           /* 64          */

    const int t  = threadIdx.x;
    const int qt = blockIdx.x;
    const int bh = blockIdx.y;
    const int b  = bh >> 4, h = bh & 15;
    const size_t base = ((size_t)b * S_LEN) * D_MODEL + (size_t)h * HD;
    const int q0 = qt * 64;
    const float scale = 0.08838834764831845f;   /* 1/sqrt(128) */

    /* load + pre-scale Q */
    for (int idx = t; idx < 64 * HD; idx += 256) {
        int i = idx >> 7, d = idx & 127;
        Qs[idx] = Qg[base + (size_t)(q0 + i) * D_MODEL + d] * scale;
    }
    if (t < 64) { m_s[t] = -1e30f; l_s[t] = 0.0f; }

    float o[32];
#pragma unroll
    for (int c = 0; c < 32; c++) o[c] = 0.0f;

    const int row_o = t & 63;        /* O-phase mapping */
    const int sub   = t >> 6;        /* col group: sub*32 .. +31 */
    const int tx    = t & 15, ty = t >> 4;   /* score-phase mapping */

    for (int kt = 0; kt <= qt; kt++) {
        const int k0 = kt * 64;
        __syncthreads();   /* KV free, Ps free */

        /* load K tile transposed: KV[d*68 + j] */
        for (int idx = t; idx < 64 * HD; idx += 256) {
            int j = idx >> 7, d = idx & 127;
            KV[d * 68 + j] = Kg[base + (size_t)(k0 + j) * D_MODEL + d];
        }
        __syncthreads();

        /* scores: acc[i][j] = Q[ty4+i] . K[tx4+j]   (Q pre-scaled) */
        {
            float acc[4][4];
#pragma unroll
            for (int i = 0; i < 4; i++)
#pragma unroll
                for (int j = 0; j < 4; j++) acc[i][j] = 0.0f;

#pragma unroll 4
            for (int dv = 0; dv < 32; dv++) {
                float qreg[4][4];   /* [row][d] */
                float kreg[4][4];   /* [d][col] */
#pragma unroll
                for (int r = 0; r < 4; r++)
                    *(float4*)qreg[r] = *(const float4*)(Qs + (ty * 4 + r) * 128 + dv * 4);
#pragma unroll
                for (int dd = 0; dd < 4; dd++)
                    *(float4*)kreg[dd] = *(const float4*)(KV + (dv * 4 + dd) * 68 + tx * 4);
#pragma unroll
                for (int i = 0; i < 4; i++)
#pragma unroll
                    for (int dd = 0; dd < 4; dd++)
#pragma unroll
                        for (int j = 0; j < 4; j++)
                            acc[i][j] += qreg[i][dd] * kreg[dd][j];
            }

            if (kt == qt) {
#pragma unroll
                for (int i = 0; i < 4; i++)
#pragma unroll
                    for (int j = 0; j < 4; j++)
                        if (tx * 4 + j > ty * 4 + i) acc[i][j] = -1e30f;
            }
#pragma unroll
            for (int i = 0; i < 4; i++) {
                float4 r;
                r.x = acc[i][0]; r.y = acc[i][1]; r.z = acc[i][2]; r.w = acc[i][3];
                *(float4*)(Ps + (ty * 4 + i) * 68 + tx * 4) = r;
            }
        }
        __syncthreads();

        /* softmax per row (threads 0..63) */
        if (t < 64) {
            const int r = t;
            float* pr   = Ps + r * 68;
            float oldm  = m_s[r];
            float mx    = oldm;
#pragma unroll 8
            for (int j = 0; j < 64; j++) mx = fmaxf(mx, pr[j]);
            float sum = 0.0f;
#pragma unroll 8
            for (int j = 0; j < 64; j++) {
                float p = expf(pr[j] - mx);
                pr[j]   = p;
                sum    += p;
            }
            float fac = expf(oldm - mx);
            l_s[r] = l_s[r] * fac + sum;
            m_s[r] = mx;
            f_s[r] = fac;
        }
        /* load V tile (row-major, pad 132) into the K buffer */
        for (int idx = t; idx < 64 * HD; idx += 256) {
            int j = idx >> 7, d = idx & 127;
            KV[j * 132 + d] = Vg[base + (size_t)(k0 + j) * D_MODEL + d];
        }
        __syncthreads();

        /* O update: o[row_o][sub*32 + c] */
        {
            float fac = f_s[row_o];
#pragma unroll
            for (int c = 0; c < 32; c++) o[c] *= fac;

            const float* prow  = Ps + row_o * 68;
            const float* vbase = KV + sub * 32;
#pragma unroll 2
            for (int j = 0; j < 64; j++) {
                float p = prow[j];
                const float4* v4 = (const float4*)(vbase + j * 132);
#pragma unroll
                for (int c4 = 0; c4 < 8; c4++) {
                    float4 v = v4[c4];
                    o[c4 * 4 + 0] += p * v.x;
                    o[c4 * 4 + 1] += p * v.y;
                    o[c4 * 4 + 2] += p * v.z;
                    o[c4 * 4 + 3] += p * v.w;
                }
            }
        }
    }

    /* normalize, stage in Qs, coalesced store */
    {
        float invl = 1.0f / l_s[row_o];
#pragma unroll
        for (int c4 = 0; c4 < 8; c4++) {
            float4 r;
            r.x = o[c4 * 4 + 0] * invl;
            r.y = o[c4 * 4 + 1] * invl;
            r.z = o[c4 * 4 + 2] * invl;
            r.w = o[c4 * 4 + 3] * invl;
            *(float4*)(Qs + row_o * 128 + sub * 32 + c4 * 4) = r;
        }
    }
    __syncthreads();
    for (int idx = t; idx < 64 * HD; idx += 256) {
        int i = idx >> 7, d = idx & 127;
        Og[base + (size_t)(q0 + i) * D_MODEL + d] = Qs[idx];
    }
}

/* ------------------------------------------------------------------ */
/* launcher                                                            */
/* ------------------------------------------------------------------ */
extern "C" void kernel_launch(void* const* d_in, const int* in_sizes, int n_in,
                              void* d_out, int out_size)
{
    (void)in_sizes; (void)n_in; (void)out_size;
    const float* x  = (const float*)d_in[0];
    const float* wq = (const float*)d_in[1];
    const float* wk = (const float*)d_in[2];
    const float* wv = (const float*)d_in[3];
    const float* wo = (const float*)d_in[4];
    float* out = (float*)d_out;

    float *pq, *pk, *pv, *pa;
    cudaGetSymbolAddress((void**)&pq, g_q);
    cudaGetSymbolAddress((void**)&pk, g_k);
    cudaGetSymbolAddress((void**)&pv, g_v);
    cudaGetSymbolAddress((void**)&pa, g_attn);

    /* RoPE tables (cheap, deterministic every call) */
    rope_table_kernel<<<(S_LEN * (HD / 2) + 255) / 256, 256>>>();

    dim3 gg(D_MODEL / 64, M_ROWS / 64);   /* (32, 64) */
    gemm_nt_kernel<<<gg, 256>>>(x, wq, pq, M_ROWS, D_MODEL, D_MODEL, 1);
    gemm_nt_kernel<<<gg, 256>>>(x, wk, pk, M_ROWS, D_MODEL, D_MODEL, 1);
    gemm_nt_kernel<<<gg, 256>>>(x, wv, pv, M_ROWS, D_MODEL, D_MODEL, 0);

    cudaFuncSetAttribute(flash_attn_kernel,
                         cudaFuncAttributeMaxDynamicSharedMemorySize,
                         FLASH_SMEM_BYTES);
    dim3 fg(S_LEN / 64, B_SZ * N_HEADS);  /* (32, 32) */
    flash_attn_kernel<<<fg, 256, FLASH_SMEM_BYTES>>>(pq, pk, pv, pa);

    gemm_nt_kernel<<<gg, 256>>>(pa, wo, out, M_ROWS, D_MODEL, D_MODEL, 0);
}

// round 7
// speedup vs baseline: 1.1744x; 1.1744x over previous
#include <cuda_runtime.h>
#include <math.h>

#define B_SZ    2
#define S_LEN   2048
#define D_MODEL 2048
#define N_HEADS 16
#define HD      128
#define M_ROWS  (B_SZ * S_LEN)   /* 4096 */

/* ------------------------------------------------------------------ */
/* scratch in device globals (no allocation allowed)                   */
/* ------------------------------------------------------------------ */
__device__ float g_q[B_SZ * S_LEN * D_MODEL];
__device__ float g_k[B_SZ * S_LEN * D_MODEL];
__device__ float g_v[B_SZ * S_LEN * D_MODEL];
__device__ float g_attn[B_SZ * S_LEN * D_MODEL];
__device__ float g_cos_tab[S_LEN * (HD / 2)];
__device__ float g_sin_tab[S_LEN * (HD / 2)];

/* ------------------------------------------------------------------ */
/* RoPE cos/sin table, computed in fp64 for accuracy                   */
/* ------------------------------------------------------------------ */
__global__ void rope_table_kernel() {
    int idx = blockIdx.x * blockDim.x + threadIdx.x;
    if (idx >= S_LEN * (HD / 2)) return;
    int s = idx >> 6;          /* position   */
    int i = idx & 63;          /* pair index */
    double inv = pow(10000.0, -(double)(2 * i) / (double)HD);
    double ang = (double)s * inv;
    g_cos_tab[idx] = (float)cos(ang);
    g_sin_tab[idx] = (float)sin(ang);
}

/* ------------------------------------------------------------------ */
/* NT GEMM:  C[m,n] = sum_k A[m,k] * W[n,k]    (K = N = D_MODEL)       */
/* 128x128 block tile, KT=16, 256 threads, 8x8 per thread (4 quadrants)*/
/* rope!=0: apply RoPE to output pairs (q/k projections).              */
/* ------------------------------------------------------------------ */
#define KT   16
#define LDP  132          /* padded leading dim for smem tiles */

__global__ void __launch_bounds__(256, 2)
gemm_nt_kernel(const float* __restrict__ A, const float* __restrict__ W,
               float* __restrict__ C, int rope)
{
    __shared__ float As[KT * LDP];
    __shared__ float Bs[KT * LDP];

    const int t  = threadIdx.x;
    const int tx = t & 15, ty = t >> 4;
    const int m0 = blockIdx.y * 128, n0 = blockIdx.x * 128;
    const int K  = D_MODEL;

    /* loaders: each thread loads 8 floats of A and 8 of W per tile */
    const int lr = t >> 1;          /* row 0..127      */
    const int lk = (t & 1) * 8;     /* k offset 0 or 8 */
    const float* aptr = A + (size_t)(m0 + lr) * K + lk;
    const float* bptr = W + (size_t)(n0 + lr) * K + lk;

    float4 a0 = *(const float4*)(aptr);
    float4 a1 = *(const float4*)(aptr + 4);
    float4 b0 = *(const float4*)(bptr);
    float4 b1 = *(const float4*)(bptr + 4);

    float acc[8][8];
#pragma unroll
    for (int i = 0; i < 8; i++)
#pragma unroll
        for (int j = 0; j < 8; j++) acc[i][j] = 0.0f;

    for (int k0 = 0; k0 < K; k0 += KT) {
        /* store prefetched tile transposed: As[k][m] */
        As[(lk + 0) * LDP + lr] = a0.x;
        As[(lk + 1) * LDP + lr] = a0.y;
        As[(lk + 2) * LDP + lr] = a0.z;
        As[(lk + 3) * LDP + lr] = a0.w;
        As[(lk + 4) * LDP + lr] = a1.x;
        As[(lk + 5) * LDP + lr] = a1.y;
        As[(lk + 6) * LDP + lr] = a1.z;
        As[(lk + 7) * LDP + lr] = a1.w;
        Bs[(lk + 0) * LDP + lr] = b0.x;
        Bs[(lk + 1) * LDP + lr] = b0.y;
        Bs[(lk + 2) * LDP + lr] = b0.z;
        Bs[(lk + 3) * LDP + lr] = b0.w;
        Bs[(lk + 4) * LDP + lr] = b1.x;
        Bs[(lk + 5) * LDP + lr] = b1.y;
        Bs[(lk + 6) * LDP + lr] = b1.z;
        Bs[(lk + 7) * LDP + lr] = b1.w;
        __syncthreads();

        if (k0 + KT < K) {
            a0 = *(const float4*)(aptr + k0 + KT);
            a1 = *(const float4*)(aptr + k0 + KT + 4);
            b0 = *(const float4*)(bptr + k0 + KT);
            b1 = *(const float4*)(bptr + k0 + KT + 4);
        }

#pragma unroll
        for (int kk = 0; kk < KT; kk++) {
            const float* ar = As + kk * LDP;
            const float* br = Bs + kk * LDP;
            float4 av0 = *(const float4*)(ar + ty * 4);
            float4 av1 = *(const float4*)(ar + 64 + ty * 4);
            float4 bv0 = *(const float4*)(br + tx * 4);
            float4 bv1 = *(const float4*)(br + 64 + tx * 4);
            float a[8] = {av0.x, av0.y, av0.z, av0.w, av1.x, av1.y, av1.z, av1.w};
            float b[8] = {bv0.x, bv0.y, bv0.z, bv0.w, bv1.x, bv1.y, bv1.z, bv1.w};
#pragma unroll
            for (int i = 0; i < 8; i++)
#pragma unroll
                for (int j = 0; j < 8; j++) acc[i][j] += a[i] * b[j];
        }
        __syncthreads();
    }

    /* epilogue: optional RoPE, then stores.
       quadrants: rows {ty*4, ty*4+64}, cols {tx*4, tx*4+64}            */
    if (rope) {
#pragma unroll
        for (int qj = 0; qj < 2; qj++) {
            const int cb = (n0 + tx * 4 + qj * 64) & (HD - 1);  /* mult of 4 */
            const int ti0 = cb >> 1;
#pragma unroll
            for (int qi = 0; qi < 2; qi++) {
#pragma unroll
                for (int i = 0; i < 4; i++) {
                    int srow = (m0 + ty * 4 + qi * 64 + i) & (S_LEN - 1);
                    const float* cbp = g_cos_tab + srow * (HD / 2);
                    const float* sbp = g_sin_tab + srow * (HD / 2);
#pragma unroll
                    for (int jp = 0; jp < 2; jp++) {
                        float c  = cbp[ti0 + jp];
                        float sn = sbp[ti0 + jp];
                        int   ai = qi * 4 + i;
                        int   aj = qj * 4 + 2 * jp;
                        float xr = acc[ai][aj];
                        float xi = acc[ai][aj + 1];
                        acc[ai][aj]     = xr * c - xi * sn;
                        acc[ai][aj + 1] = xr * sn + xi * c;
                    }
                }
            }
        }
    }

#pragma unroll
    for (int qi = 0; qi < 2; qi++) {
#pragma unroll
        for (int i = 0; i < 4; i++) {
            float* crow = C + (size_t)(m0 + ty * 4 + qi * 64 + i) * D_MODEL + n0;
            float4 r0, r1;
            r0.x = acc[qi * 4 + i][0]; r0.y = acc[qi * 4 + i][1];
            r0.z = acc[qi * 4 + i][2]; r0.w = acc[qi * 4 + i][3];
            r1.x = acc[qi * 4 + i][4]; r1.y = acc[qi * 4 + i][5];
            r1.z = acc[qi * 4 + i][6]; r1.w = acc[qi * 4 + i][7];
            *(float4*)(crow + tx * 4)      = r0;
            *(float4*)(crow + 64 + tx * 4) = r1;
        }
    }
}

/* ------------------------------------------------------------------ */
/* Flash attention (causal), fp32.  (unchanged from round 2)           */
/* ------------------------------------------------------------------ */
#define FLASH_SMEM_BYTES ((8192 + 8704 + 4352 + 192) * 4)

__global__ void __launch_bounds__(256, 2)
flash_attn_kernel(const float* __restrict__ Qg, const float* __restrict__ Kg,
                  const float* __restrict__ Vg, float* __restrict__ Og)
{
    extern __shared__ float sm[];
    float* Qs  = sm;                 /* 64*128      */
    float* KV  = sm + 8192;          /* max 128*68  */
    float* Ps  = KV + 8704;          /* 64*68       */
    float* m_s = Ps + 4352;          /* 64          */
    float* l_s = m_s + 64;           /* 64          */
    float* f_s = l_s + 64;           /* 64          */

    const int t  = threadIdx.x;
    const int qt = blockIdx.x;
    const int bh = blockIdx.y;
    const int b  = bh >> 4, h = bh & 15;
    const size_t base = ((size_t)b * S_LEN) * D_MODEL + (size_t)h * HD;
    const int q0 = qt * 64;
    const float scale = 0.08838834764831845f;   /* 1/sqrt(128) */

    for (int idx = t; idx < 64 * HD; idx += 256) {
        int i = idx >> 7, d = idx & 127;
        Qs[idx] = Qg[base + (size_t)(q0 + i) * D_MODEL + d] * scale;
    }
    if (t < 64) { m_s[t] = -1e30f; l_s[t] = 0.0f; }

    float o[32];
#pragma unroll
    for (int c = 0; c < 32; c++) o[c] = 0.0f;

    const int row_o = t & 63;
    const int sub   = t >> 6;
    const int tx    = t & 15, ty = t >> 4;

    for (int kt = 0; kt <= qt; kt++) {
        const int k0 = kt * 64;
        __syncthreads();

        for (int idx = t; idx < 64 * HD; idx += 256) {
            int j = idx >> 7, d = idx & 127;
            KV[d * 68 + j] = Kg[base + (size_t)(k0 + j) * D_MODEL + d];
        }
        __syncthreads();

        {
            float acc[4][4];
#pragma unroll
            for (int i = 0; i < 4; i++)
#pragma unroll
                for (int j = 0; j < 4; j++) acc[i][j] = 0.0f;

#pragma unroll 4
            for (int dv = 0; dv < 32; dv++) {
                float qreg[4][4];
                float kreg[4][4];
#pragma unroll
                for (int r = 0; r < 4; r++)
                    *(float4*)qreg[r] = *(const float4*)(Qs + (ty * 4 + r) * 128 + dv * 4);
#pragma unroll
                for (int dd = 0; dd < 4; dd++)
                    *(float4*)kreg[dd] = *(const float4*)(KV + (dv * 4 + dd) * 68 + tx * 4);
#pragma unroll
                for (int i = 0; i < 4; i++)
#pragma unroll
                    for (int dd = 0; dd < 4; dd++)
#pragma unroll
                        for (int j = 0; j < 4; j++)
                            acc[i][j] += qreg[i][dd] * kreg[dd][j];
            }

            if (kt == qt) {
#pragma unroll
                for (int i = 0; i < 4; i++)
#pragma unroll
                    for (int j = 0; j < 4; j++)
                        if (tx * 4 + j > ty * 4 + i) acc[i][j] = -1e30f;
            }
#pragma unroll
            for (int i = 0; i < 4; i++) {
                float4 r;
                r.x = acc[i][0]; r.y = acc[i][1]; r.z = acc[i][2]; r.w = acc[i][3];
                *(float4*)(Ps + (ty * 4 + i) * 68 + tx * 4) = r;
            }
        }
        __syncthreads();

        if (t < 64) {
            const int r = t;
            float* pr   = Ps + r * 68;
            float oldm  = m_s[r];
            float mx    = oldm;
#pragma unroll 8
            for (int j = 0; j < 64; j++) mx = fmaxf(mx, pr[j]);
            float sum = 0.0f;
#pragma unroll 8
            for (int j = 0; j < 64; j++) {
                float p = expf(pr[j] - mx);
                pr[j]   = p;
                sum    += p;
            }
            float fac = expf(oldm - mx);
            l_s[r] = l_s[r] * fac + sum;
            m_s[r] = mx;
            f_s[r] = fac;
        }
        for (int idx = t; idx < 64 * HD; idx += 256) {
            int j = idx >> 7, d = idx & 127;
            KV[j * 132 + d] = Vg[base + (size_t)(k0 + j) * D_MODEL + d];
        }
        __syncthreads();

        {
            float fac = f_s[row_o];
#pragma unroll
            for (int c = 0; c < 32; c++) o[c] *= fac;

            const float* prow  = Ps + row_o * 68;
            const float* vbase = KV + sub * 32;
#pragma unroll 2
            for (int j = 0; j < 64; j++) {
                float p = prow[j];
                const float4* v4 = (const float4*)(vbase + j * 132);
#pragma unroll
                for (int c4 = 0; c4 < 8; c4++) {
                    float4 v = v4[c4];
                    o[c4 * 4 + 0] += p * v.x;
                    o[c4 * 4 + 1] += p * v.y;
                    o[c4 * 4 + 2] += p * v.z;
                    o[c4 * 4 + 3] += p * v.w;
                }
            }
        }
    }

    {
        float invl = 1.0f / l_s[row_o];
#pragma unroll
        for (int c4 = 0; c4 < 8; c4++) {
            float4 r;
            r.x = o[c4 * 4 + 0] * invl;
            r.y = o[c4 * 4 + 1] * invl;
            r.z = o[c4 * 4 + 2] * invl;
            r.w = o[c4 * 4 + 3] * invl;
            *(float4*)(Qs + row_o * 128 + sub * 32 + c4 * 4) = r;
        }
    }
    __syncthreads();
    for (int idx = t; idx < 64 * HD; idx += 256) {
        int i = idx >> 7, d = idx & 127;
        Og[base + (size_t)(q0 + i) * D_MODEL + d] = Qs[idx];
    }
}

/* ------------------------------------------------------------------ */
/* launcher                                                            */
/* ------------------------------------------------------------------ */
extern "C" void kernel_launch(void* const* d_in, const int* in_sizes, int n_in,
                              void* d_out, int out_size)
{
    (void)in_sizes; (void)n_in; (void)out_size;
    const float* x  = (const float*)d_in[0];
    const float* wq = (const float*)d_in[1];
    const float* wk = (const float*)d_in[2];
    const float* wv = (const float*)d_in[3];
    const float* wo = (const float*)d_in[4];
    float* out = (float*)d_out;

    float *pq, *pk, *pv, *pa;
    cudaGetSymbolAddress((void**)&pq, g_q);
    cudaGetSymbolAddress((void**)&pk, g_k);
    cudaGetSymbolAddress((void**)&pv, g_v);
    cudaGetSymbolAddress((void**)&pa, g_attn);

    rope_table_kernel<<<(S_LEN * (HD / 2) + 255) / 256, 256>>>();

    dim3 gg(D_MODEL / 128, M_ROWS / 128);   /* (16, 32) */
    gemm_nt_kernel<<<gg, 256>>>(x, wq, pq, 1);
    gemm_nt_kernel<<<gg, 256>>>(x, wk, pk, 1);
    gemm_nt_kernel<<<gg, 256>>>(x, wv, pv, 0);

    cudaFuncSetAttribute(flash_attn_kernel,
                         cudaFuncAttributeMaxDynamicSharedMemorySize,
                         FLASH_SMEM_BYTES);
    dim3 fg(S_LEN / 64, B_SZ * N_HEADS);  /* (32, 32) */
    flash_attn_kernel<<<fg, 256, FLASH_SMEM_BYTES>>>(pq, pk, pv, pa);

    gemm_nt_kernel<<<gg, 256>>>(pa, wo, out, M_ROWS ? 0 : 0);
}